// round 11
// baseline (speedup 1.0000x reference)
#include <cuda_runtime.h>
#include <cstdint>

// Problem constants (fixed by the reference)
#define BB 2
#define LL 1024
#define MM 8
#define NN 16
#define CC 16
#define HH 64
#define WW 64
#define VOTES (MM * NN)            // 128
#define SLAB  (CC * HH * WW)       // 65536 floats = 256 KB per (b,l)
#define NGRP  CC                   // CGRP == 1: one channel plane per CTA
#define PLANE (HH * WW)            // 4096 floats = 16 KB per quantum

// Phase-granularity sweep continued (R2:64KB -> R9:32KB -> here:16KB quanta).
// One CTA (128 threads) = one channel plane of one (b,l) slab:
//   every thread gathers one vote -> cooperative 16 KB zero stream (STG.128,
//   8 per thread) -> __syncthreads (128-wide) -> ONE atomicAdd per thread.
// 32768 CTAs, 16 resident per SM: each CTA's barrier/atomic bubble hides
// under 15 neighbors' store streams.
__global__ __launch_bounds__(128, 16)
void ht_vote_kernel(const float* __restrict__ feats,   // [B,L,N,C]
                    const int*   __restrict__ vsrc,    // [B,L,2]
                    const int*   __restrict__ vdst,    // [B,L,2]
                    const int*   __restrict__ isrc,    // [B,L,M]
                    const int*   __restrict__ idst,    // [B,L,N]
                    float* __restrict__ out)           // [B,L,C,H,W]
{
    const int q  = blockIdx.x;         // 0 .. B*L*NGRP-1
    const int bl = q >> 4;             // NGRP == 16
    const int g  = q & 15;             // channel
    const int b  = bl >> 10;           // LL == 1024
    const int t  = threadIdx.x;        // == vote id (128 votes, 128 threads)

    // ---- Gather chain: issued before the store stream; the ~3 dependent
    // L2 latencies hide under the 16 KB of independent stores.
    const int m = t >> 4;              // NN == 16
    const int n = t & 15;

    const int s  = isrc[bl * MM + m];
    const int d  = idst[(b * LL + s) * NN + n];
    const int sy = vsrc[(b * LL + s) * 2 + 0];
    const int sx = vsrc[(b * LL + s) * 2 + 1];
    const int dy = vdst[(b * LL + d) * 2 + 0];
    const int dx = vdst[(b * LL + d) * 2 + 1];

    // voxels are int32: floor(float sub) == integer sub exactly
    const int by = dy - sy + HH / 2;
    const int bx = dx - sx + WW / 2;
    int bin = -1;
    if (((unsigned)by < HH) & ((unsigned)bx < WW)) bin = by * WW + bx;

    // this vote's weight for channel g (scalar, L2-hot; 16 sibling CTAs share)
    const float w = feats[(((size_t)(b * LL + s)) * NN + n) * CC + g];

    float* base = out + (size_t)bl * SLAB + g * PLANE;

    // ---- Stream-zero this channel plane: 16 KB, 8 float4 per thread ----
    {
        float4* b4 = (float4*)base;
        const float4 z = make_float4(0.f, 0.f, 0.f, 0.f);
#pragma unroll
        for (int i = 0; i < PLANE / 4 / 128; i++)
            b4[t + i * 128] = z;
    }

    __syncthreads();   // all zero-stores of this CTA-private plane complete
                       // & visible before any scattered atomic touches it

    // ---- Scatter: one atomicAdd per thread (REDG, L2-hot line) ----
    if (bin >= 0)
        atomicAdd(base + bin, w);
}

extern "C" void kernel_launch(void* const* d_in, const int* in_sizes, int n_in,
                              void* d_out, int out_size)
{
    const float* feats = (const float*)d_in[0];   // [B,L,N,C] f32
    const int*   vsrc  = (const int*)  d_in[1];   // [B,L,2]   i32
    const int*   vdst  = (const int*)  d_in[2];   // [B,L,2]   i32
    const int*   isrc  = (const int*)  d_in[3];   // [B,L,M]   i32
    const int*   idst  = (const int*)  d_in[4];   // [B,L,N]   i32
    float*       out   = (float*)d_out;           // [B,L,C,H,W] f32

    ht_vote_kernel<<<BB * LL * NGRP, 128>>>(feats, vsrc, vdst, isrc, idst, out);
}